// round 13
// baseline (speedup 1.0000x reference)
#include <cuda_runtime.h>
#include <cuda_bf16.h>
#include <math.h>

// ---------------- problem constants ----------------
#define MAX_NODES 200000
#define MAX_EDGES 3200000
#define SCAN_B    1024
#define TILE      256
#define PADR      36     // smem row pad: 16B-aligned float4 + conflict-free LDS.128

// ---------------- device scratch (no allocations allowed) --------------
__device__ int g_deg[MAX_NODES];
__device__ int g_rowptr[MAX_NODES + 1];
__device__ int g_fill[MAX_NODES];
__device__ int g_bsum[SCAN_B];
__device__ int g_csr[MAX_EDGES];

// ---------------- f32x2 packed helpers ----------------
__device__ __forceinline__ unsigned long long pk2(float a, float b) {
    unsigned long long r;
    asm("mov.b64 %0, {%1, %2};" : "=l"(r) : "f"(a), "f"(b));
    return r;
}
__device__ __forceinline__ void upk2(unsigned long long v, float& a, float& b) {
    asm("mov.b64 {%0, %1}, %2;" : "=f"(a), "=f"(b) : "l"(v));
}
__device__ __forceinline__ unsigned long long addx2(unsigned long long a, unsigned long long b) {
    unsigned long long r;
    asm("add.rn.f32x2 %0, %1, %2;" : "=l"(r) : "l"(a), "l"(b));
    return r;
}
__device__ __forceinline__ unsigned long long fmax2(unsigned long long a, unsigned long long b,
                                                    unsigned long long c) {
    unsigned long long r;
    asm("fma.rn.f32x2 %0, %1, %2, %3;" : "=l"(r) : "l"(a), "l"(b), "l"(c));
    return r;
}

// ---------------- CSR construction ----------------
__global__ void k_zero_deg(int* deg, int n) {
    int i = blockIdx.x * blockDim.x + threadIdx.x;
    if (i < n) deg[i] = 0;
}

__global__ void k_hist(const int* __restrict__ dst, int* deg, int E) {
    int e = blockIdx.x * blockDim.x + threadIdx.x;
    if (e < E) atomicAdd(&deg[dst[e]], 1);
}

__global__ void k_scan1(const int* __restrict__ deg, int* rowptr, int* bsum, int n) {
    __shared__ int sh[SCAN_B];
    int tid = threadIdx.x;
    int i = blockIdx.x * SCAN_B + tid;
    int d = (i < n) ? deg[i] : 0;
    sh[tid] = d;
    __syncthreads();
    int val = d;
    #pragma unroll
    for (int off = 1; off < SCAN_B; off <<= 1) {
        int t = (tid >= off) ? sh[tid - off] : 0;
        __syncthreads();
        val += t;
        sh[tid] = val;
        __syncthreads();
    }
    if (i < n) rowptr[i] = val - d;
    if (tid == SCAN_B - 1) bsum[blockIdx.x] = val;
}

__global__ void k_scan2(int* bsum, int nb) {
    __shared__ int sh[SCAN_B];
    int tid = threadIdx.x;
    int d = (tid < nb) ? bsum[tid] : 0;
    sh[tid] = d;
    __syncthreads();
    int val = d;
    #pragma unroll
    for (int off = 1; off < SCAN_B; off <<= 1) {
        int t = (tid >= off) ? sh[tid - off] : 0;
        __syncthreads();
        val += t;
        sh[tid] = val;
        __syncthreads();
    }
    if (tid < nb) bsum[tid] = val - d;
}

__global__ void k_scan3(int* rowptr, const int* __restrict__ bsum, int* fill,
                        int n, int E) {
    int i = blockIdx.x * blockDim.x + threadIdx.x;
    if (i < n) {
        int r = rowptr[i] + bsum[i >> 10];
        rowptr[i] = r;
        fill[i]   = r;
    }
    if (i == 0) rowptr[n] = E;
}

__global__ void k_fill(const int* __restrict__ src, const int* __restrict__ dst,
                       int* fill, int* csr, int E) {
    int e = blockIdx.x * blockDim.x + threadIdx.x;
    if (e < E) {
        int pos = atomicAdd(&fill[dst[e]], 1);
        csr[pos] = src[e];
    }
}

// ---------------- fused SAGE layer ----------------
// Phase A: warp-per-node gather; 4 edges per warp-load (8 lanes x LDG.128
//          cover one 128B feature row). CSR indices fetched 32-at-a-time and
//          distributed with shfl.idx. Accumulate in packed f32x2.
// Phase B: thread-per-node dense GEMV in packed f32x2; weights broadcast from
//          smem via LDS.128; output written straight into concat_states.
__global__ void __launch_bounds__(TILE)
k_sage(const float* __restrict__ h_in, int stride,
       const float* __restrict__ Ws, const float* __restrict__ Wn,
       const float* __restrict__ bias,
       const int* __restrict__ rowptr, const int* __restrict__ csr,
       float* __restrict__ cs_out, int n)
{
    __shared__ __align__(16) float sW[2048];   // [64 k][32 j]: Ws rows then Wn
    __shared__ float sB[32];
    __shared__ __align__(16) float sM[TILE * PADR];

    const int tid  = threadIdx.x;
    const int lane = tid & 31;
    const int wid  = tid >> 5;
    const int slot = lane >> 3;      // 0..3 : edge slot within a 4-edge group
    const int sub  = lane & 7;       // 0..7 : float4 position within 128B row
    const int base = blockIdx.x * TILE;

    for (int i = tid; i < 1024; i += TILE) {
        sW[i]        = Ws[i];
        sW[1024 + i] = Wn[i];
    }
    if (tid < 32) sB[tid] = bias[tid];
    __syncthreads();

    // ---- Phase A: gather means for this warp's 32 nodes ----
    #pragma unroll 1
    for (int i = 0; i < 32; i++) {
        const int v = base + wid * 32 + i;
        float4 m = make_float4(0.f, 0.f, 0.f, 0.f);
        if (v < n) {
            const int rs = __ldg(&rowptr[v]);
            const int re = __ldg(&rowptr[v + 1]);
            const int deg = re - rs;
            unsigned long long a0 = 0ull, a1 = 0ull;   // packed {f0,f1},{f2,f3}
            #pragma unroll 1
            for (int cb = rs; cb < re; cb += 32) {
                const int cnt = min(32, re - cb);
                int eidx = 0;
                if (lane < cnt) eidx = __ldg(&csr[cb + lane]);
                const int ngroups = (cnt + 3) >> 2;
                #pragma unroll 1
                for (int g = 0; g < ngroups; g++) {
                    const int pos  = g * 4 + slot;
                    const int srcv = __shfl_sync(0xffffffffu, eidx, pos);
                    if (pos < cnt) {
                        const ulonglong2* rp = reinterpret_cast<const ulonglong2*>(
                            h_in + srcv * stride);
                        ulonglong2 f = __ldg(&rp[sub]);
                        a0 = addx2(a0, f.x);
                        a1 = addx2(a1, f.y);
                    }
                }
            }
            float s0, s1, s2, s3;
            upk2(a0, s0, s1);
            upk2(a1, s2, s3);
            // reduce across the 4 slots
            s0 += __shfl_xor_sync(0xffffffffu, s0, 8);
            s1 += __shfl_xor_sync(0xffffffffu, s1, 8);
            s2 += __shfl_xor_sync(0xffffffffu, s2, 8);
            s3 += __shfl_xor_sync(0xffffffffu, s3, 8);
            s0 += __shfl_xor_sync(0xffffffffu, s0, 16);
            s1 += __shfl_xor_sync(0xffffffffu, s1, 16);
            s2 += __shfl_xor_sync(0xffffffffu, s2, 16);
            s3 += __shfl_xor_sync(0xffffffffu, s3, 16);
            const float inv = (deg > 0) ? (1.0f / (float)deg) : 0.0f;
            m = make_float4(s0 * inv, s1 * inv, s2 * inv, s3 * inv);
        }
        if (lane < 8)
            *reinterpret_cast<float4*>(&sM[(wid * 32 + i) * PADR + lane * 4]) = m;
    }
    __syncwarp();

    // ---- Phase B: thread-per-node dense transform (packed f32x2) ----
    const int v = base + tid;
    if (v >= n) return;

    const ulonglong2* sWu = reinterpret_cast<const ulonglong2*>(sW);

    unsigned long long acc2[16];
    #pragma unroll
    for (int j = 0; j < 16; j++) acc2[j] = pk2(sB[2 * j], sB[2 * j + 1]);

    // self row -> registers
    float vs[32];
    {
        const float4* selfp = reinterpret_cast<const float4*>(h_in + v * stride);
        #pragma unroll
        for (int q = 0; q < 8; q++) {
            float4 t = __ldg(&selfp[q]);
            vs[4 * q + 0] = t.x; vs[4 * q + 1] = t.y;
            vs[4 * q + 2] = t.z; vs[4 * q + 3] = t.w;
        }
    }

    // self @ Ws
    #pragma unroll
    for (int k = 0; k < 32; k++) {
        const unsigned long long vv = pk2(vs[k], vs[k]);
        #pragma unroll
        for (int q = 0; q < 8; q++) {
            ulonglong2 w = sWu[k * 8 + q];
            acc2[2 * q + 0] = fmax2(w.x, vv, acc2[2 * q + 0]);
            acc2[2 * q + 1] = fmax2(w.y, vv, acc2[2 * q + 1]);
        }
    }

    // mean row from smem -> registers (conflict-free LDS.128 with PADR=36)
    float vm[32];
    {
        const float4* mrow = reinterpret_cast<const float4*>(&sM[tid * PADR]);
        #pragma unroll
        for (int q = 0; q < 8; q++) {
            float4 t = mrow[q];
            vm[4 * q + 0] = t.x; vm[4 * q + 1] = t.y;
            vm[4 * q + 2] = t.z; vm[4 * q + 3] = t.w;
        }
    }

    // mean @ Wn
    #pragma unroll
    for (int k = 0; k < 32; k++) {
        const unsigned long long vv = pk2(vm[k], vm[k]);
        #pragma unroll
        for (int q = 0; q < 8; q++) {
            ulonglong2 w = sWu[(32 + k) * 8 + q];
            acc2[2 * q + 0] = fmax2(w.x, vv, acc2[2 * q + 0]);
            acc2[2 * q + 1] = fmax2(w.y, vv, acc2[2 * q + 1]);
        }
    }

    float4* outp = reinterpret_cast<float4*>(cs_out + v * 128);
    #pragma unroll
    for (int q = 0; q < 8; q++) {
        float x0, x1, x2, x3;
        upk2(acc2[2 * q + 0], x0, x1);
        upk2(acc2[2 * q + 1], x2, x3);
        float4 o;
        o.x = tanhf(x0); o.y = tanhf(x1);
        o.z = tanhf(x2); o.w = tanhf(x3);
        outp[q] = o;
    }
}

// ---------------- pair MLP: 8 pairs per block, W1 in shared --------------------
#define PPB 8
__global__ void __launch_bounds__(128)
k_pair(const float* __restrict__ cs, const int* __restrict__ uidx,
       const int* __restrict__ iidx,
       const float* __restrict__ W1, const float* __restrict__ bl1,
       const float* __restrict__ W2, const float* __restrict__ bl2,
       float* __restrict__ score, int n_pairs)
{
    extern __shared__ float sh[];
    float* sW1 = sh;                 // 256*128
    float* sPT = sW1 + 256 * 128;    // [256][PPB]
    float* sH  = sPT + 256 * PPB;    // [PPB][128]

    const int tid  = threadIdx.x;
    const int warp = tid >> 5;
    const int lane = tid & 31;

    for (int i = tid; i < 256 * 128; i += 128) sW1[i] = W1[i];
    const float b1 = bl1[tid];
    const float w2 = W2[tid];
    const float b2 = bl2[0];

    const int pbase = blockIdx.x * PPB;
    #pragma unroll
    for (int p = 0; p < PPB; p++) {
        int pr = pbase + p;
        int safe = (pr < n_pairs) ? pr : 0;
        int u  = uidx[safe];
        int it = iidx[safe];
        sPT[tid * PPB + p]         = cs[u  * 128 + tid];
        sPT[(128 + tid) * PPB + p] = cs[it * 128 + tid];
    }
    __syncthreads();

    float acc[PPB];
    #pragma unroll
    for (int p = 0; p < PPB; p++) acc[p] = b1;

    #pragma unroll 4
    for (int k = 0; k < 256; k++) {
        float w = sW1[k * 128 + tid];
        float4 pa = *reinterpret_cast<const float4*>(&sPT[k * PPB]);
        float4 pb = *reinterpret_cast<const float4*>(&sPT[k * PPB + 4]);
        acc[0] = fmaf(pa.x, w, acc[0]);
        acc[1] = fmaf(pa.y, w, acc[1]);
        acc[2] = fmaf(pa.z, w, acc[2]);
        acc[3] = fmaf(pa.w, w, acc[3]);
        acc[4] = fmaf(pb.x, w, acc[4]);
        acc[5] = fmaf(pb.y, w, acc[5]);
        acc[6] = fmaf(pb.z, w, acc[6]);
        acc[7] = fmaf(pb.w, w, acc[7]);
    }

    #pragma unroll
    for (int p = 0; p < PPB; p++)
        sH[p * 128 + tid] = fmaxf(acc[p], 0.0f) * w2;
    __syncthreads();

    for (int p = warp; p < PPB; p += 4) {
        float v = sH[p * 128 + lane] + sH[p * 128 + 32 + lane]
                + sH[p * 128 + 64 + lane] + sH[p * 128 + 96 + lane];
        #pragma unroll
        for (int o = 16; o > 0; o >>= 1) v += __shfl_down_sync(0xffffffffu, v, o);
        if (lane == 0 && (pbase + p) < n_pairs)
            score[pbase + p] = 1.0f / (1.0f + expf(-(v + b2)));
    }
}

// ---------------- launch ----------------
extern "C" void kernel_launch(void* const* d_in, const int* in_sizes, int n_in,
                              void* d_out, int out_size)
{
    const float* x        = (const float*)d_in[0];
    const int*   src      = (const int*)  d_in[1];
    const int*   dst      = (const int*)  d_in[2];
    const int*   user_idx = (const int*)  d_in[3];
    const int*   item_idx = (const int*)  d_in[4];
    const float* Wsx[4] = { (const float*)d_in[5],  (const float*)d_in[8],
                            (const float*)d_in[11], (const float*)d_in[14] };
    const float* Wnx[4] = { (const float*)d_in[6],  (const float*)d_in[9],
                            (const float*)d_in[12], (const float*)d_in[15] };
    const float* bx[4]  = { (const float*)d_in[7],  (const float*)d_in[10],
                            (const float*)d_in[13], (const float*)d_in[16] };
    const float* W1  = (const float*)d_in[17];
    const float* bl1 = (const float*)d_in[18];
    const float* W2  = (const float*)d_in[19];
    const float* bl2 = (const float*)d_in[20];

    const int N = in_sizes[0] / 32;
    const int E = in_sizes[1];
    const int P = in_sizes[3];

    float* out   = (float*)d_out;
    float* score = out;                 // [P]
    float* cs    = out + P;             // [N,128] concat_states

    void *p_deg, *p_rowptr, *p_fill, *p_bsum, *p_csr;
    cudaGetSymbolAddress(&p_deg,    g_deg);
    cudaGetSymbolAddress(&p_rowptr, g_rowptr);
    cudaGetSymbolAddress(&p_fill,   g_fill);
    cudaGetSymbolAddress(&p_bsum,   g_bsum);
    cudaGetSymbolAddress(&p_csr,    g_csr);
    int* deg    = (int*)p_deg;
    int* rowptr = (int*)p_rowptr;
    int* fill   = (int*)p_fill;
    int* bsum   = (int*)p_bsum;
    int* csr    = (int*)p_csr;

    // --- CSR build ---
    k_zero_deg<<<(N + 255) / 256, 256>>>(deg, N);
    k_hist<<<(E + 255) / 256, 256>>>(dst, deg, E);
    const int nb = (N + SCAN_B - 1) / SCAN_B;
    k_scan1<<<nb, SCAN_B>>>(deg, rowptr, bsum, N);
    k_scan2<<<1, SCAN_B>>>(bsum, nb);
    k_scan3<<<(N + 255) / 256, 256>>>(rowptr, bsum, fill, N, E);
    k_fill<<<(E + 255) / 256, 256>>>(src, dst, fill, csr, E);

    // --- 4 SAGE layers, writing straight into concat_states slices ---
    const int sage_grid = (N + TILE - 1) / TILE;
    k_sage<<<sage_grid, TILE>>>(x, 32, Wsx[0], Wnx[0], bx[0],
                                rowptr, csr, cs + 0, N);
    for (int l = 1; l < 4; l++) {
        k_sage<<<sage_grid, TILE>>>(cs + 32 * (l - 1), 128,
                                    Wsx[l], Wnx[l], bx[l],
                                    rowptr, csr, cs + 32 * l, N);
    }

    // --- pair MLP ---
    const int smem = (256 * 128 + 256 * PPB + PPB * 128) * (int)sizeof(float);
    cudaFuncSetAttribute(k_pair, cudaFuncAttributeMaxDynamicSharedMemorySize, smem);
    k_pair<<<(P + PPB - 1) / PPB, 128, smem>>>(cs, user_idx, item_idx,
                                               W1, bl1, W2, bl2, score, P);
}

// round 14
// speedup vs baseline: 1.0030x; 1.0030x over previous
#include <cuda_runtime.h>
#include <cuda_bf16.h>
#include <math.h>

// ---------------- problem constants ----------------
#define MAX_NODES 200000
#define MAX_EDGES 3200000
#define SCAN_B    1024
#define TILE      256
#define PADR      36     // smem row pad: 16B-aligned float4 + conflict-free LDS.128

// ---------------- device scratch (no allocations allowed) --------------
__device__ int g_deg[MAX_NODES];
__device__ int g_rowptr[MAX_NODES + 1];
__device__ int g_fill[MAX_NODES];
__device__ int g_bsum[SCAN_B];
__device__ int g_csr[MAX_EDGES];

// ---------------- f32x2 packed helpers ----------------
__device__ __forceinline__ unsigned long long pk2(float a, float b) {
    unsigned long long r;
    asm("mov.b64 %0, {%1, %2};" : "=l"(r) : "f"(a), "f"(b));
    return r;
}
__device__ __forceinline__ void upk2(unsigned long long v, float& a, float& b) {
    asm("mov.b64 {%0, %1}, %2;" : "=f"(a), "=f"(b) : "l"(v));
}
__device__ __forceinline__ unsigned long long addx2(unsigned long long a, unsigned long long b) {
    unsigned long long r;
    asm("add.rn.f32x2 %0, %1, %2;" : "=l"(r) : "l"(a), "l"(b));
    return r;
}
__device__ __forceinline__ unsigned long long fmax2(unsigned long long a, unsigned long long b,
                                                    unsigned long long c) {
    unsigned long long r;
    asm("fma.rn.f32x2 %0, %1, %2, %3;" : "=l"(r) : "l"(a), "l"(b), "l"(c));
    return r;
}

// ---------------- CSR construction ----------------
__global__ void k_zero_deg(int* deg, int n) {
    int i = blockIdx.x * blockDim.x + threadIdx.x;
    if (i < n) deg[i] = 0;
}

__global__ void k_hist(const int* __restrict__ dst, int* deg, int E) {
    int e = blockIdx.x * blockDim.x + threadIdx.x;
    if (e < E) atomicAdd(&deg[dst[e]], 1);
}

__global__ void k_scan1(const int* __restrict__ deg, int* rowptr, int* bsum, int n) {
    __shared__ int sh[SCAN_B];
    int tid = threadIdx.x;
    int i = blockIdx.x * SCAN_B + tid;
    int d = (i < n) ? deg[i] : 0;
    sh[tid] = d;
    __syncthreads();
    int val = d;
    #pragma unroll
    for (int off = 1; off < SCAN_B; off <<= 1) {
        int t = (tid >= off) ? sh[tid - off] : 0;
        __syncthreads();
        val += t;
        sh[tid] = val;
        __syncthreads();
    }
    if (i < n) rowptr[i] = val - d;
    if (tid == SCAN_B - 1) bsum[blockIdx.x] = val;
}

__global__ void k_scan2(int* bsum, int nb) {
    __shared__ int sh[SCAN_B];
    int tid = threadIdx.x;
    int d = (tid < nb) ? bsum[tid] : 0;
    sh[tid] = d;
    __syncthreads();
    int val = d;
    #pragma unroll
    for (int off = 1; off < SCAN_B; off <<= 1) {
        int t = (tid >= off) ? sh[tid - off] : 0;
        __syncthreads();
        val += t;
        sh[tid] = val;
        __syncthreads();
    }
    if (tid < nb) bsum[tid] = val - d;
}

__global__ void k_scan3(int* rowptr, const int* __restrict__ bsum, int* fill,
                        int n, int E) {
    int i = blockIdx.x * blockDim.x + threadIdx.x;
    if (i < n) {
        int r = rowptr[i] + bsum[i >> 10];
        rowptr[i] = r;
        fill[i]   = r;
    }
    if (i == 0) rowptr[n] = E;
}

__global__ void k_fill(const int* __restrict__ src, const int* __restrict__ dst,
                       int* fill, int* csr, int E) {
    int e = blockIdx.x * blockDim.x + threadIdx.x;
    if (e < E) {
        int pos = atomicAdd(&fill[dst[e]], 1);
        csr[pos] = src[e];
    }
}

// ---------------- fused SAGE layer ----------------
// Phase A: warp-per-node gather; 4 edges per warp-load (8 lanes x LDG.128
//          cover one 128B feature row). CSR indices fetched 32-at-a-time and
//          distributed with shfl.idx. Accumulate in packed f32x2.
// Phase B: thread-per-node dense GEMV in packed f32x2; weights broadcast from
//          smem via LDS.128; output written straight into concat_states.
__global__ void __launch_bounds__(TILE)
k_sage(const float* __restrict__ h_in, int stride,
       const float* __restrict__ Ws, const float* __restrict__ Wn,
       const float* __restrict__ bias,
       const int* __restrict__ rowptr, const int* __restrict__ csr,
       float* __restrict__ cs_out, int n)
{
    __shared__ __align__(16) float sW[2048];   // [64 k][32 j]: Ws rows then Wn
    __shared__ float sB[32];
    __shared__ __align__(16) float sM[TILE * PADR];

    const int tid  = threadIdx.x;
    const int lane = tid & 31;
    const int wid  = tid >> 5;
    const int slot = lane >> 3;      // 0..3 : edge slot within a 4-edge group
    const int sub  = lane & 7;       // 0..7 : float4 position within 128B row
    const int base = blockIdx.x * TILE;

    for (int i = tid; i < 1024; i += TILE) {
        sW[i]        = Ws[i];
        sW[1024 + i] = Wn[i];
    }
    if (tid < 32) sB[tid] = bias[tid];
    __syncthreads();

    // ---- Phase A: gather means for this warp's 32 nodes ----
    #pragma unroll 1
    for (int i = 0; i < 32; i++) {
        const int v = base + wid * 32 + i;
        float4 m = make_float4(0.f, 0.f, 0.f, 0.f);
        if (v < n) {
            const int rs = __ldg(&rowptr[v]);
            const int re = __ldg(&rowptr[v + 1]);
            const int deg = re - rs;
            unsigned long long a0 = 0ull, a1 = 0ull;   // packed {f0,f1},{f2,f3}
            #pragma unroll 1
            for (int cb = rs; cb < re; cb += 32) {
                const int cnt = min(32, re - cb);
                int eidx = 0;
                if (lane < cnt) eidx = __ldg(&csr[cb + lane]);
                const int ngroups = (cnt + 3) >> 2;
                #pragma unroll 1
                for (int g = 0; g < ngroups; g++) {
                    const int pos  = g * 4 + slot;
                    const int srcv = __shfl_sync(0xffffffffu, eidx, pos);
                    if (pos < cnt) {
                        const ulonglong2* rp = reinterpret_cast<const ulonglong2*>(
                            h_in + srcv * stride);
                        ulonglong2 f = __ldg(&rp[sub]);
                        a0 = addx2(a0, f.x);
                        a1 = addx2(a1, f.y);
                    }
                }
            }
            float s0, s1, s2, s3;
            upk2(a0, s0, s1);
            upk2(a1, s2, s3);
            // reduce across the 4 slots
            s0 += __shfl_xor_sync(0xffffffffu, s0, 8);
            s1 += __shfl_xor_sync(0xffffffffu, s1, 8);
            s2 += __shfl_xor_sync(0xffffffffu, s2, 8);
            s3 += __shfl_xor_sync(0xffffffffu, s3, 8);
            s0 += __shfl_xor_sync(0xffffffffu, s0, 16);
            s1 += __shfl_xor_sync(0xffffffffu, s1, 16);
            s2 += __shfl_xor_sync(0xffffffffu, s2, 16);
            s3 += __shfl_xor_sync(0xffffffffu, s3, 16);
            const float inv = (deg > 0) ? (1.0f / (float)deg) : 0.0f;
            m = make_float4(s0 * inv, s1 * inv, s2 * inv, s3 * inv);
        }
        if (lane < 8)
            *reinterpret_cast<float4*>(&sM[(wid * 32 + i) * PADR + lane * 4]) = m;
    }
    __syncwarp();

    // ---- Phase B: thread-per-node dense transform (packed f32x2) ----
    const int v = base + tid;
    if (v >= n) return;

    const ulonglong2* sWu = reinterpret_cast<const ulonglong2*>(sW);

    unsigned long long acc2[16];
    #pragma unroll
    for (int j = 0; j < 16; j++) acc2[j] = pk2(sB[2 * j], sB[2 * j + 1]);

    // self row -> registers
    float vs[32];
    {
        const float4* selfp = reinterpret_cast<const float4*>(h_in + v * stride);
        #pragma unroll
        for (int q = 0; q < 8; q++) {
            float4 t = __ldg(&selfp[q]);
            vs[4 * q + 0] = t.x; vs[4 * q + 1] = t.y;
            vs[4 * q + 2] = t.z; vs[4 * q + 3] = t.w;
        }
    }

    // self @ Ws
    #pragma unroll
    for (int k = 0; k < 32; k++) {
        const unsigned long long vv = pk2(vs[k], vs[k]);
        #pragma unroll
        for (int q = 0; q < 8; q++) {
            ulonglong2 w = sWu[k * 8 + q];
            acc2[2 * q + 0] = fmax2(w.x, vv, acc2[2 * q + 0]);
            acc2[2 * q + 1] = fmax2(w.y, vv, acc2[2 * q + 1]);
        }
    }

    // mean row from smem -> registers (conflict-free LDS.128 with PADR=36)
    float vm[32];
    {
        const float4* mrow = reinterpret_cast<const float4*>(&sM[tid * PADR]);
        #pragma unroll
        for (int q = 0; q < 8; q++) {
            float4 t = mrow[q];
            vm[4 * q + 0] = t.x; vm[4 * q + 1] = t.y;
            vm[4 * q + 2] = t.z; vm[4 * q + 3] = t.w;
        }
    }

    // mean @ Wn
    #pragma unroll
    for (int k = 0; k < 32; k++) {
        const unsigned long long vv = pk2(vm[k], vm[k]);
        #pragma unroll
        for (int q = 0; q < 8; q++) {
            ulonglong2 w = sWu[(32 + k) * 8 + q];
            acc2[2 * q + 0] = fmax2(w.x, vv, acc2[2 * q + 0]);
            acc2[2 * q + 1] = fmax2(w.y, vv, acc2[2 * q + 1]);
        }
    }

    float4* outp = reinterpret_cast<float4*>(cs_out + v * 128);
    #pragma unroll
    for (int q = 0; q < 8; q++) {
        float x0, x1, x2, x3;
        upk2(acc2[2 * q + 0], x0, x1);
        upk2(acc2[2 * q + 1], x2, x3);
        float4 o;
        o.x = tanhf(x0); o.y = tanhf(x1);
        o.z = tanhf(x2); o.w = tanhf(x3);
        outp[q] = o;
    }
}

// ---------------- pair MLP: 8 pairs per block, W1 in shared --------------------
#define PPB 8
__global__ void __launch_bounds__(128)
k_pair(const float* __restrict__ cs, const int* __restrict__ uidx,
       const int* __restrict__ iidx,
       const float* __restrict__ W1, const float* __restrict__ bl1,
       const float* __restrict__ W2, const float* __restrict__ bl2,
       float* __restrict__ score, int n_pairs)
{
    extern __shared__ float sh[];
    float* sW1 = sh;                 // 256*128
    float* sPT = sW1 + 256 * 128;    // [256][PPB]
    float* sH  = sPT + 256 * PPB;    // [PPB][128]

    const int tid  = threadIdx.x;
    const int warp = tid >> 5;
    const int lane = tid & 31;

    for (int i = tid; i < 256 * 128; i += 128) sW1[i] = W1[i];
    const float b1 = bl1[tid];
    const float w2 = W2[tid];
    const float b2 = bl2[0];

    const int pbase = blockIdx.x * PPB;
    #pragma unroll
    for (int p = 0; p < PPB; p++) {
        int pr = pbase + p;
        int safe = (pr < n_pairs) ? pr : 0;
        int u  = uidx[safe];
        int it = iidx[safe];
        sPT[tid * PPB + p]         = cs[u  * 128 + tid];
        sPT[(128 + tid) * PPB + p] = cs[it * 128 + tid];
    }
    __syncthreads();

    float acc[PPB];
    #pragma unroll
    for (int p = 0; p < PPB; p++) acc[p] = b1;

    #pragma unroll 4
    for (int k = 0; k < 256; k++) {
        float w = sW1[k * 128 + tid];
        float4 pa = *reinterpret_cast<const float4*>(&sPT[k * PPB]);
        float4 pb = *reinterpret_cast<const float4*>(&sPT[k * PPB + 4]);
        acc[0] = fmaf(pa.x, w, acc[0]);
        acc[1] = fmaf(pa.y, w, acc[1]);
        acc[2] = fmaf(pa.z, w, acc[2]);
        acc[3] = fmaf(pa.w, w, acc[3]);
        acc[4] = fmaf(pb.x, w, acc[4]);
        acc[5] = fmaf(pb.y, w, acc[5]);
        acc[6] = fmaf(pb.z, w, acc[6]);
        acc[7] = fmaf(pb.w, w, acc[7]);
    }

    #pragma unroll
    for (int p = 0; p < PPB; p++)
        sH[p * 128 + tid] = fmaxf(acc[p], 0.0f) * w2;
    __syncthreads();

    for (int p = warp; p < PPB; p += 4) {
        float v = sH[p * 128 + lane] + sH[p * 128 + 32 + lane]
                + sH[p * 128 + 64 + lane] + sH[p * 128 + 96 + lane];
        #pragma unroll
        for (int o = 16; o > 0; o >>= 1) v += __shfl_down_sync(0xffffffffu, v, o);
        if (lane == 0 && (pbase + p) < n_pairs)
            score[pbase + p] = 1.0f / (1.0f + expf(-(v + b2)));
    }
}

// ---------------- launch ----------------
extern "C" void kernel_launch(void* const* d_in, const int* in_sizes, int n_in,
                              void* d_out, int out_size)
{
    const float* x        = (const float*)d_in[0];
    const int*   src      = (const int*)  d_in[1];
    const int*   dst      = (const int*)  d_in[2];
    const int*   user_idx = (const int*)  d_in[3];
    const int*   item_idx = (const int*)  d_in[4];
    const float* Wsx[4] = { (const float*)d_in[5],  (const float*)d_in[8],
                            (const float*)d_in[11], (const float*)d_in[14] };
    const float* Wnx[4] = { (const float*)d_in[6],  (const float*)d_in[9],
                            (const float*)d_in[12], (const float*)d_in[15] };
    const float* bx[4]  = { (const float*)d_in[7],  (const float*)d_in[10],
                            (const float*)d_in[13], (const float*)d_in[16] };
    const float* W1  = (const float*)d_in[17];
    const float* bl1 = (const float*)d_in[18];
    const float* W2  = (const float*)d_in[19];
    const float* bl2 = (const float*)d_in[20];

    const int N = in_sizes[0] / 32;
    const int E = in_sizes[1];
    const int P = in_sizes[3];

    float* out   = (float*)d_out;
    float* score = out;                 // [P]
    float* cs    = out + P;             // [N,128] concat_states

    void *p_deg, *p_rowptr, *p_fill, *p_bsum, *p_csr;
    cudaGetSymbolAddress(&p_deg,    g_deg);
    cudaGetSymbolAddress(&p_rowptr, g_rowptr);
    cudaGetSymbolAddress(&p_fill,   g_fill);
    cudaGetSymbolAddress(&p_bsum,   g_bsum);
    cudaGetSymbolAddress(&p_csr,    g_csr);
    int* deg    = (int*)p_deg;
    int* rowptr = (int*)p_rowptr;
    int* fill   = (int*)p_fill;
    int* bsum   = (int*)p_bsum;
    int* csr    = (int*)p_csr;

    // --- CSR build ---
    k_zero_deg<<<(N + 255) / 256, 256>>>(deg, N);
    k_hist<<<(E + 255) / 256, 256>>>(dst, deg, E);
    const int nb = (N + SCAN_B - 1) / SCAN_B;
    k_scan1<<<nb, SCAN_B>>>(deg, rowptr, bsum, N);
    k_scan2<<<1, SCAN_B>>>(bsum, nb);
    k_scan3<<<(N + 255) / 256, 256>>>(rowptr, bsum, fill, N, E);
    k_fill<<<(E + 255) / 256, 256>>>(src, dst, fill, csr, E);

    // --- 4 SAGE layers, writing straight into concat_states slices ---
    const int sage_grid = (N + TILE - 1) / TILE;
    k_sage<<<sage_grid, TILE>>>(x, 32, Wsx[0], Wnx[0], bx[0],
                                rowptr, csr, cs + 0, N);
    for (int l = 1; l < 4; l++) {
        k_sage<<<sage_grid, TILE>>>(cs + 32 * (l - 1), 128,
                                    Wsx[l], Wnx[l], bx[l],
                                    rowptr, csr, cs + 32 * l, N);
    }

    // --- pair MLP ---
    const int smem = (256 * 128 + 256 * PPB + PPB * 128) * (int)sizeof(float);
    cudaFuncSetAttribute(k_pair, cudaFuncAttributeMaxDynamicSharedMemorySize, smem);
    k_pair<<<(P + PPB - 1) / PPB, 128, smem>>>(cs, user_idx, item_idx,
                                               W1, bl1, W2, bl2, score, P);
}

// round 15
// speedup vs baseline: 1.1597x; 1.1562x over previous
#include <cuda_runtime.h>
#include <cuda_bf16.h>
#include <math.h>

// ---------------- problem constants ----------------
#define MAX_NODES 200000
#define MAX_EDGES 3200000
#define SCAN_B    1024

// ---------------- device scratch (no allocations allowed) --------------
__device__ int   g_deg[MAX_NODES];
__device__ int   g_rowptr[MAX_NODES + 1];
__device__ int   g_fill[MAX_NODES];
__device__ int   g_bsum[SCAN_B];
__device__ int   g_csr[MAX_EDGES];
__device__ float g_mean[MAX_NODES * 32];

// ---------------- f32x2 packed helpers ----------------
__device__ __forceinline__ unsigned long long pk2(float a, float b) {
    unsigned long long r;
    asm("mov.b64 %0, {%1, %2};" : "=l"(r) : "f"(a), "f"(b));
    return r;
}
__device__ __forceinline__ void upk2(unsigned long long v, float& a, float& b) {
    asm("mov.b64 {%0, %1}, %2;" : "=f"(a), "=f"(b) : "l"(v));
}
__device__ __forceinline__ unsigned long long fmax2(unsigned long long a, unsigned long long b,
                                                    unsigned long long c) {
    unsigned long long r;
    asm("fma.rn.f32x2 %0, %1, %2, %3;" : "=l"(r) : "l"(a), "l"(b), "l"(c));
    return r;
}

// ---------------- CSR construction ----------------
__global__ void k_zero_deg(int* deg, int n) {
    int i = blockIdx.x * blockDim.x + threadIdx.x;
    if (i < n) deg[i] = 0;
}

__global__ void k_hist(const int* __restrict__ dst, int* deg, int E) {
    int e = blockIdx.x * blockDim.x + threadIdx.x;
    if (e < E) atomicAdd(&deg[dst[e]], 1);
}

__global__ void k_scan1(const int* __restrict__ deg, int* rowptr, int* bsum, int n) {
    __shared__ int sh[SCAN_B];
    int tid = threadIdx.x;
    int i = blockIdx.x * SCAN_B + tid;
    int d = (i < n) ? deg[i] : 0;
    sh[tid] = d;
    __syncthreads();
    int val = d;
    #pragma unroll
    for (int off = 1; off < SCAN_B; off <<= 1) {
        int t = (tid >= off) ? sh[tid - off] : 0;
        __syncthreads();
        val += t;
        sh[tid] = val;
        __syncthreads();
    }
    if (i < n) rowptr[i] = val - d;
    if (tid == SCAN_B - 1) bsum[blockIdx.x] = val;
}

__global__ void k_scan2(int* bsum, int nb) {
    __shared__ int sh[SCAN_B];
    int tid = threadIdx.x;
    int d = (tid < nb) ? bsum[tid] : 0;
    sh[tid] = d;
    __syncthreads();
    int val = d;
    #pragma unroll
    for (int off = 1; off < SCAN_B; off <<= 1) {
        int t = (tid >= off) ? sh[tid - off] : 0;
        __syncthreads();
        val += t;
        sh[tid] = val;
        __syncthreads();
    }
    if (tid < nb) bsum[tid] = val - d;
}

__global__ void k_scan3(int* rowptr, const int* __restrict__ bsum, int* fill,
                        int n, int E) {
    int i = blockIdx.x * blockDim.x + threadIdx.x;
    if (i < n) {
        int r = rowptr[i] + bsum[i >> 10];
        rowptr[i] = r;
        fill[i]   = r;
    }
    if (i == 0) rowptr[n] = E;
}

__global__ void k_fill(const int* __restrict__ src, const int* __restrict__ dst,
                       int* fill, int* csr, int E) {
    int e = blockIdx.x * blockDim.x + threadIdx.x;
    if (e < E) {
        int pos = atomicAdd(&fill[dst[e]], 1);
        csr[pos] = src[e];
    }
}

// ---------------- gather: warp-per-node neighbor mean ----------------
// Lean kernel (no smem, ~55 regs) -> high occupancy; 16 independent feature
// loads in flight per warp in the main loop; single predicated tail chunk.
__global__ void __launch_bounds__(256)
k_gather(const float* __restrict__ h_in, int stride,
         const int* __restrict__ rowptr, const int* __restrict__ csr,
         float* __restrict__ meanb, int n)
{
    const int lane = threadIdx.x & 31;
    const int v = (blockIdx.x * blockDim.x + threadIdx.x) >> 5;
    if (v >= n) return;

    const int rs = __ldg(&rowptr[v]);
    const int re = __ldg(&rowptr[v + 1]);
    const int deg = re - rs;

    float a[8];
    #pragma unroll
    for (int i = 0; i < 8; i++) a[i] = 0.f;

    int e = rs;
    #pragma unroll 1
    for (; e + 16 <= re; e += 16) {
        int s[16];
        #pragma unroll
        for (int i = 0; i < 16; i++) s[i] = __ldg(&csr[e + i]);
        float f[16];
        #pragma unroll
        for (int i = 0; i < 16; i++) f[i] = __ldg(&h_in[s[i] * stride + lane]);
        #pragma unroll
        for (int i = 0; i < 16; i++) a[i & 7] += f[i];
    }
    // tail: at most 15 edges, fully predicated (no serial dependent chain)
    {
        int   s[15];
        float f[15];
        #pragma unroll
        for (int i = 0; i < 15; i++) {
            const bool p = (e + i) < re;
            s[i] = p ? __ldg(&csr[e + i]) : 0;
        }
        #pragma unroll
        for (int i = 0; i < 15; i++) {
            const bool p = (e + i) < re;
            f[i] = p ? __ldg(&h_in[s[i] * stride + lane]) : 0.f;
        }
        #pragma unroll
        for (int i = 0; i < 15; i++) a[i & 7] += f[i];
    }

    const float acc = ((a[0] + a[1]) + (a[2] + a[3])) + ((a[4] + a[5]) + (a[6] + a[7]));
    const float inv = (deg > 0) ? (1.0f / (float)deg) : 0.0f;
    meanb[v * 32 + lane] = acc * inv;
}

// ---------------- dense: thread-per-node GEMV (packed f32x2) ----------------
// out = tanh([self; mean] @ [Ws; Wn] + b), written into concat_states slice.
__global__ void __launch_bounds__(256)
k_dense(const float* __restrict__ h_in, int stride,
        const float* __restrict__ meanb,
        const float* __restrict__ Ws, const float* __restrict__ Wn,
        const float* __restrict__ bias,
        float* __restrict__ cs_out, int n)
{
    __shared__ __align__(16) float sW[2048];   // [64 k][32 j]: Ws rows then Wn
    __shared__ float sB[32];

    const int tid = threadIdx.x;
    for (int i = tid; i < 1024; i += 256) {
        sW[i]        = Ws[i];
        sW[1024 + i] = Wn[i];
    }
    if (tid < 32) sB[tid] = bias[tid];
    __syncthreads();

    const int v = blockIdx.x * blockDim.x + tid;
    if (v >= n) return;

    const ulonglong2* sWu = reinterpret_cast<const ulonglong2*>(sW);

    unsigned long long acc2[16];
    #pragma unroll
    for (int j = 0; j < 16; j++) acc2[j] = pk2(sB[2 * j], sB[2 * j + 1]);

    // self row
    float vs[32];
    {
        const float4* selfp = reinterpret_cast<const float4*>(h_in + v * stride);
        #pragma unroll
        for (int q = 0; q < 8; q++) {
            float4 t = __ldg(&selfp[q]);
            vs[4 * q + 0] = t.x; vs[4 * q + 1] = t.y;
            vs[4 * q + 2] = t.z; vs[4 * q + 3] = t.w;
        }
    }
    #pragma unroll
    for (int k = 0; k < 32; k++) {
        const unsigned long long vv = pk2(vs[k], vs[k]);
        #pragma unroll
        for (int q = 0; q < 8; q++) {
            ulonglong2 w = sWu[k * 8 + q];
            acc2[2 * q + 0] = fmax2(w.x, vv, acc2[2 * q + 0]);
            acc2[2 * q + 1] = fmax2(w.y, vv, acc2[2 * q + 1]);
        }
    }

    // mean row
    float vm[32];
    {
        const float4* mrow = reinterpret_cast<const float4*>(meanb + v * 32);
        #pragma unroll
        for (int q = 0; q < 8; q++) {
            float4 t = __ldg(&mrow[q]);
            vm[4 * q + 0] = t.x; vm[4 * q + 1] = t.y;
            vm[4 * q + 2] = t.z; vm[4 * q + 3] = t.w;
        }
    }
    #pragma unroll
    for (int k = 0; k < 32; k++) {
        const unsigned long long vv = pk2(vm[k], vm[k]);
        #pragma unroll
        for (int q = 0; q < 8; q++) {
            ulonglong2 w = sWu[(32 + k) * 8 + q];
            acc2[2 * q + 0] = fmax2(w.x, vv, acc2[2 * q + 0]);
            acc2[2 * q + 1] = fmax2(w.y, vv, acc2[2 * q + 1]);
        }
    }

    float4* outp = reinterpret_cast<float4*>(cs_out + v * 128);
    #pragma unroll
    for (int q = 0; q < 8; q++) {
        float x0, x1, x2, x3;
        upk2(acc2[2 * q + 0], x0, x1);
        upk2(acc2[2 * q + 1], x2, x3);
        float4 o;
        o.x = tanhf(x0); o.y = tanhf(x1);
        o.z = tanhf(x2); o.w = tanhf(x3);
        outp[q] = o;
    }
}

// ---------------- pair MLP: 8 pairs per block, W1 in shared --------------------
#define PPB 8
__global__ void __launch_bounds__(128)
k_pair(const float* __restrict__ cs, const int* __restrict__ uidx,
       const int* __restrict__ iidx,
       const float* __restrict__ W1, const float* __restrict__ bl1,
       const float* __restrict__ W2, const float* __restrict__ bl2,
       float* __restrict__ score, int n_pairs)
{
    extern __shared__ float sh[];
    float* sW1 = sh;                 // 256*128
    float* sPT = sW1 + 256 * 128;    // [256][PPB]
    float* sH  = sPT + 256 * PPB;    // [PPB][128]

    const int tid  = threadIdx.x;
    const int warp = tid >> 5;
    const int lane = tid & 31;

    for (int i = tid; i < 256 * 128; i += 128) sW1[i] = W1[i];
    const float b1 = bl1[tid];
    const float w2 = W2[tid];
    const float b2 = bl2[0];

    const int pbase = blockIdx.x * PPB;
    #pragma unroll
    for (int p = 0; p < PPB; p++) {
        int pr = pbase + p;
        int safe = (pr < n_pairs) ? pr : 0;
        int u  = uidx[safe];
        int it = iidx[safe];
        sPT[tid * PPB + p]         = cs[u  * 128 + tid];
        sPT[(128 + tid) * PPB + p] = cs[it * 128 + tid];
    }
    __syncthreads();

    float acc[PPB];
    #pragma unroll
    for (int p = 0; p < PPB; p++) acc[p] = b1;

    #pragma unroll 4
    for (int k = 0; k < 256; k++) {
        float w = sW1[k * 128 + tid];
        float4 pa = *reinterpret_cast<const float4*>(&sPT[k * PPB]);
        float4 pb = *reinterpret_cast<const float4*>(&sPT[k * PPB + 4]);
        acc[0] = fmaf(pa.x, w, acc[0]);
        acc[1] = fmaf(pa.y, w, acc[1]);
        acc[2] = fmaf(pa.z, w, acc[2]);
        acc[3] = fmaf(pa.w, w, acc[3]);
        acc[4] = fmaf(pb.x, w, acc[4]);
        acc[5] = fmaf(pb.y, w, acc[5]);
        acc[6] = fmaf(pb.z, w, acc[6]);
        acc[7] = fmaf(pb.w, w, acc[7]);
    }

    #pragma unroll
    for (int p = 0; p < PPB; p++)
        sH[p * 128 + tid] = fmaxf(acc[p], 0.0f) * w2;
    __syncthreads();

    for (int p = warp; p < PPB; p += 4) {
        float v = sH[p * 128 + lane] + sH[p * 128 + 32 + lane]
                + sH[p * 128 + 64 + lane] + sH[p * 128 + 96 + lane];
        #pragma unroll
        for (int o = 16; o > 0; o >>= 1) v += __shfl_down_sync(0xffffffffu, v, o);
        if (lane == 0 && (pbase + p) < n_pairs)
            score[pbase + p] = 1.0f / (1.0f + expf(-(v + b2)));
    }
}

// ---------------- launch ----------------
extern "C" void kernel_launch(void* const* d_in, const int* in_sizes, int n_in,
                              void* d_out, int out_size)
{
    const float* x        = (const float*)d_in[0];
    const int*   src      = (const int*)  d_in[1];
    const int*   dst      = (const int*)  d_in[2];
    const int*   user_idx = (const int*)  d_in[3];
    const int*   item_idx = (const int*)  d_in[4];
    const float* Wsx[4] = { (const float*)d_in[5],  (const float*)d_in[8],
                            (const float*)d_in[11], (const float*)d_in[14] };
    const float* Wnx[4] = { (const float*)d_in[6],  (const float*)d_in[9],
                            (const float*)d_in[12], (const float*)d_in[15] };
    const float* bx[4]  = { (const float*)d_in[7],  (const float*)d_in[10],
                            (const float*)d_in[13], (const float*)d_in[16] };
    const float* W1  = (const float*)d_in[17];
    const float* bl1 = (const float*)d_in[18];
    const float* W2  = (const float*)d_in[19];
    const float* bl2 = (const float*)d_in[20];

    const int N = in_sizes[0] / 32;
    const int E = in_sizes[1];
    const int P = in_sizes[3];

    float* out   = (float*)d_out;
    float* score = out;                 // [P]
    float* cs    = out + P;             // [N,128] concat_states

    void *p_deg, *p_rowptr, *p_fill, *p_bsum, *p_csr, *p_mean;
    cudaGetSymbolAddress(&p_deg,    g_deg);
    cudaGetSymbolAddress(&p_rowptr, g_rowptr);
    cudaGetSymbolAddress(&p_fill,   g_fill);
    cudaGetSymbolAddress(&p_bsum,   g_bsum);
    cudaGetSymbolAddress(&p_csr,    g_csr);
    cudaGetSymbolAddress(&p_mean,   g_mean);
    int*   deg    = (int*)p_deg;
    int*   rowptr = (int*)p_rowptr;
    int*   fill   = (int*)p_fill;
    int*   bsum   = (int*)p_bsum;
    int*   csr    = (int*)p_csr;
    float* meanb  = (float*)p_mean;

    // --- CSR build ---
    k_zero_deg<<<(N + 255) / 256, 256>>>(deg, N);
    k_hist<<<(E + 255) / 256, 256>>>(dst, deg, E);
    const int nb = (N + SCAN_B - 1) / SCAN_B;
    k_scan1<<<nb, SCAN_B>>>(deg, rowptr, bsum, N);
    k_scan2<<<1, SCAN_B>>>(bsum, nb);
    k_scan3<<<(N + 255) / 256, 256>>>(rowptr, bsum, fill, N, E);
    k_fill<<<(E + 255) / 256, 256>>>(src, dst, fill, csr, E);

    // --- 4 SAGE layers: gather (warp/node) + dense (thread/node) ---
    const int ggrid = (N * 32 + 255) / 256;   // 8 warps/block, 1 node/warp
    const int dgrid = (N + 255) / 256;
    for (int l = 0; l < 4; l++) {
        const float* hin   = (l == 0) ? x  : cs + 32 * (l - 1);
        const int    strid = (l == 0) ? 32 : 128;
        k_gather<<<ggrid, 256>>>(hin, strid, rowptr, csr, meanb, N);
        k_dense <<<dgrid, 256>>>(hin, strid, meanb, Wsx[l], Wnx[l], bx[l],
                                 cs + 32 * l, N);
    }

    // --- pair MLP ---
    const int smem = (256 * 128 + 256 * PPB + PPB * 128) * (int)sizeof(float);
    cudaFuncSetAttribute(k_pair, cudaFuncAttributeMaxDynamicSharedMemorySize, smem);
    k_pair<<<(P + PPB - 1) / PPB, 128, smem>>>(cs, user_idx, item_idx,
                                               W1, bl1, W2, bl2, score, P);
}